// round 2
// baseline (speedup 1.0000x reference)
#include <cuda_runtime.h>

#define N_NODES   8192
#define T_TYPES   4
#define E_EDGES   131072        // = 2^17
#define H_HEADS   4
#define D_DIM     32
#define NEG_SLOPE 0.2f

#define HASH_BITS 22
#define HASH_SIZE (1u << HASH_BITS)
#define HASH_MASK (HASH_SIZE - 1u)
#define MAX_WORK  (T_TYPES * E_EDGES)   // upper bound on distinct keys

// Scratch — zero-initialized at module load; every kernel call leaves it
// zeroed again (self-cleaning), so no big clear kernel is needed.
__device__ unsigned int g_keys[HASH_SIZE];    // 0 = empty, else key+1
__device__ unsigned int g_cnts[HASH_SIZE];    // 4 byte-packed per-type counts
__device__ unsigned int g_work[MAX_WORK];     // slots owned (compact)
__device__ unsigned int g_nwork;              // worklist length
__device__ float4 g_acc[N_NODES * 2];         // per node: [d0,n0,d1,n1][d2,n2,d3,n3]
__device__ float g_wsrc[H_HEADS];
__device__ float g_wtgt[H_HEADS];
__device__ float g_embterm[H_HEADS * T_TYPES];
__device__ float g_stotal;

// ---------------------------------------------------------------------------
// 1) Tiny per-head parameters + total score sum (single block)
// ---------------------------------------------------------------------------
__global__ void k_params(const float* __restrict__ scores,
                         const float* __restrict__ emb,
                         const float* __restrict__ W) {
    __shared__ float red[256];
    int tid = threadIdx.x;

    float s = 0.f;
    for (int i = tid; i < N_NODES; i += 256) s += scores[i];
    red[tid] = s;
    __syncthreads();
    for (int o = 128; o > 0; o >>= 1) {
        if (tid < o) red[tid] += red[tid + o];
        __syncthreads();
    }
    if (tid == 0) g_stotal = red[0];

    if (tid < H_HEADS * T_TYPES) {
        int h = tid / T_TYPES, t = tid % T_TYPES;
        float acc = 0.f;
        #pragma unroll
        for (int d = 0; d < D_DIM; d++)
            acc += emb[t * D_DIM + d] * W[h * (D_DIM + 2) + 1 + d];
        g_embterm[h * T_TYPES + t] = acc;
    }
    if (tid >= 32 && tid < 32 + H_HEADS) {
        int h = tid - 32;
        g_wsrc[h] = W[h * (D_DIM + 2)];
        g_wtgt[h] = W[h * (D_DIM + 2) + D_DIM + 1];
    }
}

// ---------------------------------------------------------------------------
// 2) Insert edges; CAS winner (unique per distinct key) appends slot to
//    worklist via warp-aggregated atomic.
// ---------------------------------------------------------------------------
__global__ void k_insert(const int* __restrict__ ei) {
    int id = blockIdx.x * blockDim.x + threadIdx.x;
    int t = id >> 17;             // E_EDGES = 2^17
    int e = id & (E_EDGES - 1);
    unsigned int src = (unsigned int)ei[(t * 2    ) * E_EDGES + e];
    unsigned int tgt = (unsigned int)ei[(t * 2 + 1) * E_EDGES + e];

    unsigned int key = ((src << 13) | tgt) + 1u;   // nonzero
    unsigned int h = key * 2654435761u;
    h ^= h >> 15;
    unsigned int slot = h & HASH_MASK;

    bool won = false;
    while (true) {
        unsigned int old = atomicCAS(&g_keys[slot], 0u, key);
        if (old == 0u)  { won = true; break; }
        if (old == key) break;
        slot = (slot + 1) & HASH_MASK;
    }
    atomicAdd(&g_cnts[slot], 1u << (t * 8));

    // warp-aggregated append of winning slots
    unsigned int mask = __ballot_sync(0xffffffffu, won);
    if (won) {
        unsigned int lane   = threadIdx.x & 31;
        unsigned int leader = __ffs(mask) - 1u;
        unsigned int base = 0;
        if (lane == leader) base = atomicAdd(&g_nwork, (unsigned)__popc(mask));
        base = __shfl_sync(0xffffffffu, base, leader);
        g_work[base + __popc(mask & ((1u << lane) - 1u))] = slot;
    }
}

// ---------------------------------------------------------------------------
// 3) Process worklist: reconstruct summed a_ij per head, REDG.v4 the
//    (exp-1, (exp-1)*s_j) pairs into per-node accumulators; self-clean slots.
// ---------------------------------------------------------------------------
__global__ void k_process(const float* __restrict__ scores) {
    unsigned int id = blockIdx.x * blockDim.x + threadIdx.x;
    if (id >= g_nwork) return;
    unsigned int slot = g_work[id];
    unsigned int key = g_keys[slot] - 1u;
    unsigned int c   = g_cnts[slot];
    g_keys[slot] = 0u;     // self-clean for the next graph replay
    g_cnts[slot] = 0u;

    float c0 = (float)( c        & 0xFFu);
    float c1 = (float)((c >> 8 ) & 0xFFu);
    float c2 = (float)((c >> 16) & 0xFFu);
    float c3 = (float)((c >> 24) & 0xFFu);
    float ctot = c0 + c1 + c2 + c3;

    unsigned int i = key >> 13;
    unsigned int j = key & 8191u;
    float si = __ldg(scores + i);
    float sj = __ldg(scores + j);

    float ex[H_HEADS];
    #pragma unroll
    for (int h = 0; h < H_HEADS; h++) {
        float a = (si * g_wsrc[h] + sj * g_wtgt[h]) * ctot
                + c0 * g_embterm[h * T_TYPES + 0]
                + c1 * g_embterm[h * T_TYPES + 1]
                + c2 * g_embterm[h * T_TYPES + 2]
                + c3 * g_embterm[h * T_TYPES + 3];
        a = (a >= 0.f) ? a : NEG_SLOPE * a;
        ex[h] = __expf(a) - 1.f;
    }

    float4* dst = &g_acc[i * 2];
    asm volatile("red.global.add.v4.f32 [%0], {%1,%2,%3,%4};"
                 :: "l"(dst), "f"(ex[0]), "f"(ex[0] * sj),
                    "f"(ex[1]), "f"(ex[1] * sj) : "memory");
    asm volatile("red.global.add.v4.f32 [%0], {%1,%2,%3,%4};"
                 :: "l"(dst + 1), "f"(ex[2]), "f"(ex[2] * sj),
                    "f"(ex[3]), "f"(ex[3] * sj) : "memory");
}

// ---------------------------------------------------------------------------
// 4) Finalize: out_i = mean_h (S_total + num_h) / (N + denom_h); reset scratch.
// ---------------------------------------------------------------------------
__global__ void k_final(float* __restrict__ out) {
    int i = blockIdx.x * blockDim.x + threadIdx.x;
    if (i >= N_NODES) return;
    float st = g_stotal;
    float4 a0 = g_acc[i * 2];
    float4 a1 = g_acc[i * 2 + 1];
    float acc = (st + a0.y) / ((float)N_NODES + a0.x)
              + (st + a0.w) / ((float)N_NODES + a0.z)
              + (st + a1.y) / ((float)N_NODES + a1.x)
              + (st + a1.w) / ((float)N_NODES + a1.z);
    out[i] = acc * (1.f / (float)H_HEADS);
    g_acc[i * 2]     = make_float4(0.f, 0.f, 0.f, 0.f);
    g_acc[i * 2 + 1] = make_float4(0.f, 0.f, 0.f, 0.f);
    if (i == 0) g_nwork = 0u;
}

// ---------------------------------------------------------------------------
extern "C" void kernel_launch(void* const* d_in, const int* in_sizes, int n_in,
                              void* d_out, int out_size) {
    const float* scores = (const float*)d_in[0];   // (N, 1)
    const float* emb    = (const float*)d_in[1];   // (T, D)
    const int*   ei     = (const int*)  d_in[2];   // (T, 2, E)
    const float* W      = (const float*)d_in[3];   // (H, D+2, 1)
    float*       out    = (float*)d_out;           // (N, 1)

    k_params <<<1, 256>>>(scores, emb, W);
    k_insert <<<(T_TYPES * E_EDGES) / 256, 256>>>(ei);
    k_process<<<MAX_WORK / 256, 256>>>(scores);
    k_final  <<<N_NODES / 256, 256>>>(out);
}

// round 3
// speedup vs baseline: 1.5205x; 1.5205x over previous
#include <cuda_runtime.h>

#define N_NODES   8192
#define T_TYPES   4
#define E_EDGES   131072        // = 2^17
#define H_HEADS   4
#define D_DIM     32
#define NEG_SLOPE 0.2f

#define HASH_BITS 21
#define HASH_SIZE (1u << HASH_BITS)
#define HASH_MASK (HASH_SIZE - 1u)

// Scratch — zero-initialized at module load; every kernel call leaves it
// zeroed again (self-cleaning in k_process / k_final), so no clear kernel.
__device__ unsigned int g_keys[HASH_SIZE];    // 0 = empty, else key+1
__device__ unsigned int g_cnts[HASH_SIZE];    // 4 byte-packed per-type counts
__device__ float4 g_acc[N_NODES * 2];         // per node: [d0,n0,d1,n1][d2,n2,d3,n3]
__device__ float g_wsrc[H_HEADS];
__device__ float g_wtgt[H_HEADS];
__device__ float g_embterm[H_HEADS * T_TYPES];
__device__ float g_stotal;

// ---------------------------------------------------------------------------
// 1) Tiny per-head parameters + total score sum (single block)
// ---------------------------------------------------------------------------
__global__ void k_params(const float* __restrict__ scores,
                         const float* __restrict__ emb,
                         const float* __restrict__ W) {
    __shared__ float red[256];
    int tid = threadIdx.x;

    float s = 0.f;
    for (int i = tid; i < N_NODES; i += 256) s += scores[i];
    red[tid] = s;
    __syncthreads();
    for (int o = 128; o > 0; o >>= 1) {
        if (tid < o) red[tid] += red[tid + o];
        __syncthreads();
    }
    if (tid == 0) g_stotal = red[0];

    if (tid < H_HEADS * T_TYPES) {
        int h = tid / T_TYPES, t = tid % T_TYPES;
        float acc = 0.f;
        #pragma unroll
        for (int d = 0; d < D_DIM; d++)
            acc += emb[t * D_DIM + d] * W[h * (D_DIM + 2) + 1 + d];
        g_embterm[h * T_TYPES + t] = acc;
    }
    if (tid >= 32 && tid < 32 + H_HEADS) {
        int h = tid - 32;
        g_wsrc[h] = W[h * (D_DIM + 2)];
        g_wtgt[h] = W[h * (D_DIM + 2) + D_DIM + 1];
    }
}

// ---------------------------------------------------------------------------
// 2) Insert all edges into the hash: key=(src<<13)|tgt (+1, so 0 = empty),
//    per-type counts byte-packed into one uint32. No worklist, no hot atomics.
// ---------------------------------------------------------------------------
__global__ void k_insert(const int* __restrict__ ei) {
    int id = blockIdx.x * blockDim.x + threadIdx.x;
    int t = id >> 17;             // E_EDGES = 2^17
    int e = id & (E_EDGES - 1);
    unsigned int src = (unsigned int)ei[(t * 2    ) * E_EDGES + e];
    unsigned int tgt = (unsigned int)ei[(t * 2 + 1) * E_EDGES + e];

    unsigned int key = ((src << 13) | tgt) + 1u;   // nonzero
    unsigned int h = key * 2654435761u;
    h ^= h >> 15;
    unsigned int slot = h & HASH_MASK;

    while (true) {
        unsigned int old = atomicCAS(&g_keys[slot], 0u, key);
        if (old == 0u || old == key) break;
        slot = (slot + 1) & HASH_MASK;
    }
    atomicAdd(&g_cnts[slot], 1u << (t * 8));
}

// ---------------------------------------------------------------------------
// 3) Coalesced scan of all slots; occupied slots: self-clean, reconstruct the
//    summed a_ij per head, REDG.v4 the (exp-1, (exp-1)*s_j) pairs per node.
// ---------------------------------------------------------------------------
__global__ void k_process(const float* __restrict__ scores) {
    unsigned int s = blockIdx.x * blockDim.x + threadIdx.x;
    unsigned int keyp = g_keys[s];
    if (keyp == 0u) return;
    unsigned int c = g_cnts[s];
    g_keys[s] = 0u;     // self-clean for the next graph replay
    g_cnts[s] = 0u;

    unsigned int key = keyp - 1u;

    float c0 = (float)( c        & 0xFFu);
    float c1 = (float)((c >> 8 ) & 0xFFu);
    float c2 = (float)((c >> 16) & 0xFFu);
    float c3 = (float)((c >> 24) & 0xFFu);
    float ctot = c0 + c1 + c2 + c3;

    unsigned int i = key >> 13;
    unsigned int j = key & 8191u;
    float si = __ldg(scores + i);
    float sj = __ldg(scores + j);

    float ex[H_HEADS];
    #pragma unroll
    for (int h = 0; h < H_HEADS; h++) {
        float a = (si * g_wsrc[h] + sj * g_wtgt[h]) * ctot
                + c0 * g_embterm[h * T_TYPES + 0]
                + c1 * g_embterm[h * T_TYPES + 1]
                + c2 * g_embterm[h * T_TYPES + 2]
                + c3 * g_embterm[h * T_TYPES + 3];
        a = (a >= 0.f) ? a : NEG_SLOPE * a;
        ex[h] = __expf(a) - 1.f;
    }

    float4* dst = &g_acc[i * 2];
    asm volatile("red.global.add.v4.f32 [%0], {%1,%2,%3,%4};"
                 :: "l"(dst), "f"(ex[0]), "f"(ex[0] * sj),
                    "f"(ex[1]), "f"(ex[1] * sj) : "memory");
    asm volatile("red.global.add.v4.f32 [%0], {%1,%2,%3,%4};"
                 :: "l"(dst + 1), "f"(ex[2]), "f"(ex[2] * sj),
                    "f"(ex[3]), "f"(ex[3] * sj) : "memory");
}

// ---------------------------------------------------------------------------
// 4) Finalize: out_i = mean_h (S_total + num_h) / (N + denom_h); reset g_acc.
// ---------------------------------------------------------------------------
__global__ void k_final(float* __restrict__ out) {
    int i = blockIdx.x * blockDim.x + threadIdx.x;
    if (i >= N_NODES) return;
    float st = g_stotal;
    float4 a0 = g_acc[i * 2];
    float4 a1 = g_acc[i * 2 + 1];
    float acc = (st + a0.y) / ((float)N_NODES + a0.x)
              + (st + a0.w) / ((float)N_NODES + a0.z)
              + (st + a1.y) / ((float)N_NODES + a1.x)
              + (st + a1.w) / ((float)N_NODES + a1.z);
    out[i] = acc * (1.f / (float)H_HEADS);
    g_acc[i * 2]     = make_float4(0.f, 0.f, 0.f, 0.f);
    g_acc[i * 2 + 1] = make_float4(0.f, 0.f, 0.f, 0.f);
}

// ---------------------------------------------------------------------------
extern "C" void kernel_launch(void* const* d_in, const int* in_sizes, int n_in,
                              void* d_out, int out_size) {
    const float* scores = (const float*)d_in[0];   // (N, 1)
    const float* emb    = (const float*)d_in[1];   // (T, D)
    const int*   ei     = (const int*)  d_in[2];   // (T, 2, E)
    const float* W      = (const float*)d_in[3];   // (H, D+2, 1)
    float*       out    = (float*)d_out;           // (N, 1)

    k_params <<<1, 256>>>(scores, emb, W);
    k_insert <<<(T_TYPES * E_EDGES) / 256, 256>>>(ei);
    k_process<<<HASH_SIZE / 256, 256>>>(scores);
    k_final  <<<N_NODES / 256, 256>>>(out);
}

// round 4
// speedup vs baseline: 1.8094x; 1.1899x over previous
#include <cuda_runtime.h>

#define N_NODES   8192
#define T_TYPES   4
#define E_EDGES   131072        // = 2^17
#define H_HEADS   4
#define D_DIM     32
#define NEG_SLOPE 0.2f

#define HASH_BITS 21
#define HASH_SIZE (1u << HASH_BITS)
#define HASH_MASK (HASH_SIZE - 1u)

#define PREP_BLOCKS (N_NODES / 256)              // 32
#define INS_BLOCKS  ((T_TYPES * E_EDGES) / 256)  // 2048

// Scratch — zero-init at module load; self-cleaned every call.
__device__ unsigned int g_keys[HASH_SIZE];    // 0 = empty, else key+1
__device__ unsigned int g_cnts[HASH_SIZE];    // 4 byte-packed per-type counts
__device__ float4 g_acc[N_NODES * 2];         // per node: [d0,n0,d1,n1][d2,n2,d3,n3]
// Factorized exp tables (rebuilt every call; no cleaning needed — overwritten).
__device__ float4 g_srcP[N_NODES * 2];        // [2i]=exp(si*wsrc_h), [2i+1]=exp(.2*si*wsrc_h)
__device__ float4 g_tgtP[N_NODES * 2];        // [2j]=exp(sj*wtgt_h), [2j+1]=exp(.2*...)
__device__ float4 g_Gt [T_TYPES];             // exp(embterm[h][t]) over h
__device__ float4 g_G5t[T_TYPES];             // exp(.2*embterm[h][t])
__device__ float g_wsrc[H_HEADS];             // fallback-path params
__device__ float g_wtgt[H_HEADS];
__device__ float g_embterm[H_HEADS * T_TYPES];
__device__ float g_stotal;

// ---------------------------------------------------------------------------
// 1) Fused build: blocks [0,32) build per-node exp tables + params + S_total;
//    blocks [32, 32+2048) insert edges into the hash.
// ---------------------------------------------------------------------------
__global__ void k_build(const float* __restrict__ scores,
                        const float* __restrict__ emb,
                        const float* __restrict__ W,
                        const int*   __restrict__ ei) {
    if (blockIdx.x < PREP_BLOCKS) {
        int i = blockIdx.x * 256 + threadIdx.x;
        float s = scores[i];
        float E[4], E5[4], F[4], F5[4];
        #pragma unroll
        for (int h = 0; h < H_HEADS; h++) {
            float ws = __ldg(W + h * (D_DIM + 2));
            float wt = __ldg(W + h * (D_DIM + 2) + D_DIM + 1);
            E [h] = __expf(s * ws);
            E5[h] = __expf(NEG_SLOPE * s * ws);
            F [h] = __expf(s * wt);
            F5[h] = __expf(NEG_SLOPE * s * wt);
        }
        g_srcP[2 * i    ] = make_float4(E [0], E [1], E [2], E [3]);
        g_srcP[2 * i + 1] = make_float4(E5[0], E5[1], E5[2], E5[3]);
        g_tgtP[2 * i    ] = make_float4(F [0], F [1], F [2], F [3]);
        g_tgtP[2 * i + 1] = make_float4(F5[0], F5[1], F5[2], F5[3]);

        if (blockIdx.x == 0) {
            // Deterministic full score sum (single block, no atomics/reset).
            __shared__ float red[256];
            int tid = threadIdx.x;
            float ss = 0.f;
            for (int k = tid; k < N_NODES; k += 256) ss += scores[k];
            red[tid] = ss;
            __syncthreads();
            for (int o = 128; o > 0; o >>= 1) {
                if (tid < o) red[tid] += red[tid + o];
                __syncthreads();
            }
            if (tid == 0) g_stotal = red[0];

            if (tid < H_HEADS * T_TYPES) {
                int t = tid >> 2, h = tid & 3;
                float acc = 0.f;
                #pragma unroll
                for (int d = 0; d < D_DIM; d++)
                    acc += emb[t * D_DIM + d] * W[h * (D_DIM + 2) + 1 + d];
                g_embterm[h * T_TYPES + t] = acc;
                ((float*)g_Gt )[t * 4 + h] = __expf(acc);
                ((float*)g_G5t)[t * 4 + h] = __expf(NEG_SLOPE * acc);
            }
            if (tid >= 64 && tid < 64 + H_HEADS) {
                int h = tid - 64;
                g_wsrc[h] = W[h * (D_DIM + 2)];
                g_wtgt[h] = W[h * (D_DIM + 2) + D_DIM + 1];
            }
        }
    } else {
        int id = (blockIdx.x - PREP_BLOCKS) * 256 + threadIdx.x;
        int t = id >> 17;             // E_EDGES = 2^17
        int e = id & (E_EDGES - 1);
        unsigned int src = (unsigned int)ei[(t * 2    ) * E_EDGES + e];
        unsigned int tgt = (unsigned int)ei[(t * 2 + 1) * E_EDGES + e];

        unsigned int key = ((src << 13) | tgt) + 1u;   // nonzero
        unsigned int h = key * 2654435761u;
        h ^= h >> 15;
        unsigned int slot = h & HASH_MASK;

        while (true) {
            unsigned int old = atomicCAS(&g_keys[slot], 0u, key);
            if (old == 0u || old == key) break;
            slot = (slot + 1) & HASH_MASK;
        }
        atomicAdd(&g_cnts[slot], 1u << (t * 8));
    }
}

// ---------------------------------------------------------------------------
// 2) Scan slots. Singleton fast path: ex_h from precomputed exp products,
//    branch via (E*F*G >= 1) — zero MUFU. Rare multi path: __expf fallback.
// ---------------------------------------------------------------------------
__global__ void k_process(const float* __restrict__ scores) {
    unsigned int s = blockIdx.x * blockDim.x + threadIdx.x;
    unsigned int keyp = g_keys[s];
    if (keyp == 0u) return;
    unsigned int c = g_cnts[s];
    g_keys[s] = 0u;     // self-clean for the next graph replay
    g_cnts[s] = 0u;

    unsigned int key = keyp - 1u;
    unsigned int i = key >> 13;
    unsigned int j = key & 8191u;
    float sj = __ldg(scores + j);

    float ex[H_HEADS];
    // singleton: exactly one edge (count 1 in exactly one type byte)
    if ((c & (c - 1u)) == 0u && (c & 0x01010101u)) {
        int t = (__ffs(c) - 1) >> 3;
        float4 E  = g_srcP[2 * i], E5 = g_srcP[2 * i + 1];
        float4 F  = g_tgtP[2 * j], F5 = g_tgtP[2 * j + 1];
        float4 G  = g_Gt[t],       G5 = g_G5t[t];
        float p, q;
        p = E.x * F.x * G.x;  q = E5.x * F5.x * G5.x;  ex[0] = (p >= 1.f ? p : q) - 1.f;
        p = E.y * F.y * G.y;  q = E5.y * F5.y * G5.y;  ex[1] = (p >= 1.f ? p : q) - 1.f;
        p = E.z * F.z * G.z;  q = E5.z * F5.z * G5.z;  ex[2] = (p >= 1.f ? p : q) - 1.f;
        p = E.w * F.w * G.w;  q = E5.w * F5.w * G5.w;  ex[3] = (p >= 1.f ? p : q) - 1.f;
    } else {
        float si = __ldg(scores + i);
        float c0 = (float)( c        & 0xFFu);
        float c1 = (float)((c >> 8 ) & 0xFFu);
        float c2 = (float)((c >> 16) & 0xFFu);
        float c3 = (float)((c >> 24) & 0xFFu);
        float ctot = c0 + c1 + c2 + c3;
        #pragma unroll
        for (int h = 0; h < H_HEADS; h++) {
            float a = (si * g_wsrc[h] + sj * g_wtgt[h]) * ctot
                    + c0 * g_embterm[h * T_TYPES + 0]
                    + c1 * g_embterm[h * T_TYPES + 1]
                    + c2 * g_embterm[h * T_TYPES + 2]
                    + c3 * g_embterm[h * T_TYPES + 3];
            a = (a >= 0.f) ? a : NEG_SLOPE * a;
            ex[h] = __expf(a) - 1.f;
        }
    }

    float4* dst = &g_acc[i * 2];
    asm volatile("red.global.add.v4.f32 [%0], {%1,%2,%3,%4};"
                 :: "l"(dst), "f"(ex[0]), "f"(ex[0] * sj),
                    "f"(ex[1]), "f"(ex[1] * sj) : "memory");
    asm volatile("red.global.add.v4.f32 [%0], {%1,%2,%3,%4};"
                 :: "l"(dst + 1), "f"(ex[2]), "f"(ex[2] * sj),
                    "f"(ex[3]), "f"(ex[3] * sj) : "memory");
}

// ---------------------------------------------------------------------------
// 3) Finalize: out_i = mean_h (S_total + num_h) / (N + denom_h); reset g_acc.
// ---------------------------------------------------------------------------
__global__ void k_final(float* __restrict__ out) {
    int i = blockIdx.x * blockDim.x + threadIdx.x;
    if (i >= N_NODES) return;
    float st = g_stotal;
    float4 a0 = g_acc[i * 2];
    float4 a1 = g_acc[i * 2 + 1];
    float acc = (st + a0.y) / ((float)N_NODES + a0.x)
              + (st + a0.w) / ((float)N_NODES + a0.z)
              + (st + a1.y) / ((float)N_NODES + a1.x)
              + (st + a1.w) / ((float)N_NODES + a1.z);
    out[i] = acc * (1.f / (float)H_HEADS);
    g_acc[i * 2]     = make_float4(0.f, 0.f, 0.f, 0.f);
    g_acc[i * 2 + 1] = make_float4(0.f, 0.f, 0.f, 0.f);
}

// ---------------------------------------------------------------------------
extern "C" void kernel_launch(void* const* d_in, const int* in_sizes, int n_in,
                              void* d_out, int out_size) {
    const float* scores = (const float*)d_in[0];   // (N, 1)
    const float* emb    = (const float*)d_in[1];   // (T, D)
    const int*   ei     = (const int*)  d_in[2];   // (T, 2, E)
    const float* W      = (const float*)d_in[3];   // (H, D+2, 1)
    float*       out    = (float*)d_out;           // (N, 1)

    k_build  <<<PREP_BLOCKS + INS_BLOCKS, 256>>>(scores, emb, W, ei);
    k_process<<<HASH_SIZE / 256, 256>>>(scores);
    k_final  <<<N_NODES / 256, 256>>>(out);
}

// round 5
// speedup vs baseline: 2.9446x; 1.6275x over previous
#include <cuda_runtime.h>

#define N_NODES   8192
#define T_TYPES   4
#define E_EDGES   131072        // = 2^17
#define H_HEADS   4
#define D_DIM     32
#define NEG_SLOPE 0.2f

#define BMP_WORDS (1u << 21)    // 2^26 keys / 32 bits = 8 MiB bitmap
#define DUP_BITS  16
#define DUP_SIZE  (1u << DUP_BITS)
#define DUP_MASK  (DUP_SIZE - 1u)

#define PREP_BLOCKS (N_NODES / 256)              // 32
#define EDGE_BLOCKS ((T_TYPES * E_EDGES) / 256)  // 2048

// Scratch — zero-init at module load; K3 re-clears what K1/K2 dirtied.
__device__ unsigned int g_bmp[BMP_WORDS];          // seen-bit per (i,j) key
__device__ unsigned int g_dkey[DUP_SIZE];          // dup hash: 0=empty else key+1
__device__ unsigned int g_dmul[DUP_SIZE];          // extra-arrival count (m-1)
__device__ unsigned long long g_dagg[DUP_SIZE];    // lo32: packed type counts, hi32: arrivals
__device__ float4 g_acc[N_NODES * 2];              // [d0,n0,d1,n1][d2,n2,d3,n3]
__device__ float4 g_srcP[N_NODES * 2];             // exp(si*wsrc_h), exp(.2*si*wsrc_h)
__device__ float4 g_tgtP[N_NODES * 2];             // exp(sj*wtgt_h), exp(.2*sj*wtgt_h)
__device__ float4 g_Gt [T_TYPES];                  // exp(embterm[h][t])
__device__ float4 g_G5t[T_TYPES];                  // exp(.2*embterm[h][t])
__device__ float g_wsrc[H_HEADS];
__device__ float g_wtgt[H_HEADS];
__device__ float g_embterm[H_HEADS * T_TYPES];
__device__ float g_stotal;

__device__ __forceinline__ unsigned int hashk(unsigned int key) {
    unsigned int h = key * 2654435761u;
    return h ^ (h >> 15);
}

// ---------------------------------------------------------------------------
// K1: blocks [0,32) build exp tables + params; blocks [32,2080) detect dups.
// ---------------------------------------------------------------------------
__global__ void k_build(const float* __restrict__ scores,
                        const float* __restrict__ emb,
                        const float* __restrict__ W,
                        const int*   __restrict__ ei) {
    if (blockIdx.x < PREP_BLOCKS) {
        int i = blockIdx.x * 256 + threadIdx.x;
        float s = scores[i];
        float E[4], E5[4], F[4], F5[4];
        #pragma unroll
        for (int h = 0; h < H_HEADS; h++) {
            float ws = __ldg(W + h * (D_DIM + 2));
            float wt = __ldg(W + h * (D_DIM + 2) + D_DIM + 1);
            E [h] = __expf(s * ws);
            E5[h] = __expf(NEG_SLOPE * s * ws);
            F [h] = __expf(s * wt);
            F5[h] = __expf(NEG_SLOPE * s * wt);
        }
        g_srcP[2 * i    ] = make_float4(E [0], E [1], E [2], E [3]);
        g_srcP[2 * i + 1] = make_float4(E5[0], E5[1], E5[2], E5[3]);
        g_tgtP[2 * i    ] = make_float4(F [0], F [1], F [2], F [3]);
        g_tgtP[2 * i + 1] = make_float4(F5[0], F5[1], F5[2], F5[3]);

        if (blockIdx.x == 0) {
            __shared__ float red[256];
            int tid = threadIdx.x;
            float ss = 0.f;
            for (int k = tid; k < N_NODES; k += 256) ss += scores[k];
            red[tid] = ss;
            __syncthreads();
            for (int o = 128; o > 0; o >>= 1) {
                if (tid < o) red[tid] += red[tid + o];
                __syncthreads();
            }
            if (tid == 0) g_stotal = red[0];

            if (tid < H_HEADS * T_TYPES) {
                int t = tid >> 2, h = tid & 3;
                float acc = 0.f;
                #pragma unroll
                for (int d = 0; d < D_DIM; d++)
                    acc += emb[t * D_DIM + d] * W[h * (D_DIM + 2) + 1 + d];
                g_embterm[h * T_TYPES + t] = acc;
                ((float*)g_Gt )[t * 4 + h] = __expf(acc);
                ((float*)g_G5t)[t * 4 + h] = __expf(NEG_SLOPE * acc);
            }
            if (tid >= 64 && tid < 64 + H_HEADS) {
                int h = tid - 64;
                g_wsrc[h] = W[h * (D_DIM + 2)];
                g_wtgt[h] = W[h * (D_DIM + 2) + D_DIM + 1];
            }
        }
    } else {
        int id = (blockIdx.x - PREP_BLOCKS) * 256 + threadIdx.x;
        int t = id >> 17;
        int e = id & (E_EDGES - 1);
        unsigned int src = (unsigned int)ei[(t * 2    ) * E_EDGES + e];
        unsigned int tgt = (unsigned int)ei[(t * 2 + 1) * E_EDGES + e];
        unsigned int key = (src << 13) | tgt;

        unsigned int bit = 1u << (key & 31u);
        unsigned int old = atomicOr(&g_bmp[key >> 5], bit);
        if (old & bit) {
            // second+ occurrence of this key: register in tiny dup hash
            unsigned int hh = hashk(key) & DUP_MASK;
            while (true) {
                unsigned int o = atomicCAS(&g_dkey[hh], 0u, key + 1u);
                if (o == 0u || o == key + 1u) break;
                hh = (hh + 1u) & DUP_MASK;
            }
            atomicAdd(&g_dmul[hh], 1u);
        }
    }
}

// ---------------------------------------------------------------------------
// K2: stream edges. Singleton fast path (no MUFU); dup groups aggregated via
// packed u64 atomic, last arriver computes the group term via __expf.
// ---------------------------------------------------------------------------
__global__ void k_edges(const float* __restrict__ scores,
                        const int*   __restrict__ ei) {
    int id = blockIdx.x * 256 + threadIdx.x;
    int t = id >> 17;
    int e = id & (E_EDGES - 1);
    unsigned int src = (unsigned int)ei[(t * 2    ) * E_EDGES + e];
    unsigned int tgt = (unsigned int)ei[(t * 2 + 1) * E_EDGES + e];
    unsigned int key = (src << 13) | tgt;

    // probe tiny dup hash (read-only here; complete after K1)
    unsigned int hh = hashk(key) & DUP_MASK;
    int dslot = -1;
    while (true) {
        unsigned int k2 = g_dkey[hh];
        if (k2 == 0u) break;
        if (k2 == key + 1u) { dslot = (int)hh; break; }
        hh = (hh + 1u) & DUP_MASK;
    }

    float sj = __ldg(scores + tgt);
    float ex0, ex1, ex2, ex3;

    if (dslot < 0) {
        float4 E  = g_srcP[2 * src], E5 = g_srcP[2 * src + 1];
        float4 F  = g_tgtP[2 * tgt], F5 = g_tgtP[2 * tgt + 1];
        float4 G  = g_Gt[t],         G5 = g_G5t[t];
        float p, q;
        p = E.x * F.x * G.x;  q = E5.x * F5.x * G5.x;  ex0 = (p >= 1.f ? p : q) - 1.f;
        p = E.y * F.y * G.y;  q = E5.y * F5.y * G5.y;  ex1 = (p >= 1.f ? p : q) - 1.f;
        p = E.z * F.z * G.z;  q = E5.z * F5.z * G5.z;  ex2 = (p >= 1.f ? p : q) - 1.f;
        p = E.w * F.w * G.w;  q = E5.w * F5.w * G5.w;  ex3 = (p >= 1.f ? p : q) - 1.f;
    } else {
        unsigned long long inc = (1ULL << 32) | (unsigned long long)(1u << (t * 8));
        unsigned long long old = atomicAdd(&g_dagg[dslot], inc);
        unsigned int arrived = (unsigned int)(old >> 32);
        unsigned int m = g_dmul[dslot] + 1u;          // total multiplicity
        if (arrived != m - 1u) return;                // not the last arriver
        unsigned int c = (unsigned int)(old & 0xFFFFFFFFull) + (1u << (t * 8));
        float si = __ldg(scores + src);
        float c0 = (float)( c        & 0xFFu);
        float c1 = (float)((c >> 8 ) & 0xFFu);
        float c2 = (float)((c >> 16) & 0xFFu);
        float c3 = (float)((c >> 24) & 0xFFu);
        float ctot = c0 + c1 + c2 + c3;
        float exh[4];
        #pragma unroll
        for (int h = 0; h < H_HEADS; h++) {
            float a = (si * g_wsrc[h] + sj * g_wtgt[h]) * ctot
                    + c0 * g_embterm[h * T_TYPES + 0]
                    + c1 * g_embterm[h * T_TYPES + 1]
                    + c2 * g_embterm[h * T_TYPES + 2]
                    + c3 * g_embterm[h * T_TYPES + 3];
            a = (a >= 0.f) ? a : NEG_SLOPE * a;
            exh[h] = __expf(a) - 1.f;
        }
        ex0 = exh[0]; ex1 = exh[1]; ex2 = exh[2]; ex3 = exh[3];
    }

    float4* dst = &g_acc[src * 2];
    asm volatile("red.global.add.v4.f32 [%0], {%1,%2,%3,%4};"
                 :: "l"(dst), "f"(ex0), "f"(ex0 * sj),
                    "f"(ex1), "f"(ex1 * sj) : "memory");
    asm volatile("red.global.add.v4.f32 [%0], {%1,%2,%3,%4};"
                 :: "l"(dst + 1), "f"(ex2), "f"(ex2 * sj),
                    "f"(ex3), "f"(ex3 * sj) : "memory");
}

// ---------------------------------------------------------------------------
// K3: blocks [0,32) finalize + reset g_acc; remaining blocks clear bitmap
// and dup-hash scratch for the next graph replay.
// ---------------------------------------------------------------------------
__global__ void k_final(float* __restrict__ out) {
    if (blockIdx.x < PREP_BLOCKS) {
        int i = blockIdx.x * 256 + threadIdx.x;
        float st = g_stotal;
        float4 a0 = g_acc[i * 2];
        float4 a1 = g_acc[i * 2 + 1];
        float acc = (st + a0.y) / ((float)N_NODES + a0.x)
                  + (st + a0.w) / ((float)N_NODES + a0.z)
                  + (st + a1.y) / ((float)N_NODES + a1.x)
                  + (st + a1.w) / ((float)N_NODES + a1.z);
        out[i] = acc * (1.f / (float)H_HEADS);
        g_acc[i * 2]     = make_float4(0.f, 0.f, 0.f, 0.f);
        g_acc[i * 2 + 1] = make_float4(0.f, 0.f, 0.f, 0.f);
    } else {
        unsigned int tidc   = (blockIdx.x - PREP_BLOCKS) * 256 + threadIdx.x;
        unsigned int stride = (gridDim.x - PREP_BLOCKS) * 256;
        uint4 z4 = make_uint4(0u, 0u, 0u, 0u);
        uint4* bmp4 = (uint4*)g_bmp;                  // 2^19 uint4
        for (unsigned int k = tidc; k < (BMP_WORDS >> 2); k += stride) bmp4[k] = z4;
        for (unsigned int k = tidc; k < DUP_SIZE; k += stride) {
            g_dkey[k] = 0u;
            g_dmul[k] = 0u;
            g_dagg[k] = 0ull;
        }
    }
}

// ---------------------------------------------------------------------------
extern "C" void kernel_launch(void* const* d_in, const int* in_sizes, int n_in,
                              void* d_out, int out_size) {
    const float* scores = (const float*)d_in[0];   // (N, 1)
    const float* emb    = (const float*)d_in[1];   // (T, D)
    const int*   ei     = (const int*)  d_in[2];   // (T, 2, E)
    const float* W      = (const float*)d_in[3];   // (H, D+2, 1)
    float*       out    = (float*)d_out;           // (N, 1)

    k_build<<<PREP_BLOCKS + EDGE_BLOCKS, 256>>>(scores, emb, W, ei);
    k_edges<<<EDGE_BLOCKS, 256>>>(scores, ei);
    k_final<<<PREP_BLOCKS + 2016, 256>>>(out);
}